// round 6
// baseline (speedup 1.0000x reference)
#include <cuda_runtime.h>
#include <cstdint>

#define N_NODES 20000
#define N_EDGES 320000

typedef unsigned long long u64;

// ---------------- device scratch -----------------------------------------------
__device__ __align__(16) float g_h[N_NODES * 64];              // h = nf@w_up/8
__device__ __align__(16) float g_agg[(size_t)N_NODES * 576];   // m-major planes

// ---------------- helpers -------------------------------------------------------
__device__ __forceinline__ uint32_t f2tf32(float x) {
    uint32_t r; asm("cvt.rna.tf32.f32 %0, %1;" : "=r"(r) : "f"(x)); return r;
}
__device__ __forceinline__ uint2 split2(float x) {
    uint2 p; p.x = f2tf32(x); p.y = f2tf32(x - __uint_as_float(p.x)); return p;
}
__device__ __forceinline__ void red4(float* p, float a, float b, float c, float d) {
    asm volatile("red.global.add.v4.f32 [%0], {%1, %2, %3, %4};"
                 :: "l"((u64)__cvta_generic_to_global(p)),
                    "f"(a), "f"(b), "f"(c), "f"(d) : "memory");
}
#define MMA8(C, a0, a1, a2, a3, b0, b1) \
    asm volatile("mma.sync.aligned.m16n8k8.row.col.f32.tf32.tf32.f32 " \
        "{%0,%1,%2,%3}, {%4,%5,%6,%7}, {%8,%9}, {%0,%1,%2,%3};" \
        : "+f"((C)[0]), "+f"((C)[1]), "+f"((C)[2]), "+f"((C)[3]) \
        : "r"(a0), "r"(a1), "r"(a2), "r"(a3), "r"(b0), "r"(b1))

// ---------------- kernel 0: zero agg -------------------------------------------
__global__ void k_zero() {
    size_t i = (size_t)blockIdx.x * 256 + threadIdx.x;
    reinterpret_cast<float4*>(g_agg)[i] = make_float4(0.f, 0.f, 0.f, 0.f);
}

// ---------------- kernel 1: h = nf @ w_up * (1/8) -------------------------------
__global__ void __launch_bounds__(256) k_node_up(const float* __restrict__ nf,
                                                 const float* __restrict__ w) {
    __shared__ __align__(16) float sW[64 * 64];
    __shared__ float sA[32 * 65];
    const int t  = threadIdx.x;
    const int nb = blockIdx.x * 32;
    for (int i = t; i < 4096; i += 256) sW[i] = w[i];
    for (int i = t; i < 2048; i += 256) sA[(i >> 6) * 65 + (i & 63)] = nf[nb * 64 + i];
    __syncthreads();
    const int ty = t >> 4, tx = t & 15;
    const int r0 = ty * 2, c0 = tx * 4;
    float acc[2][4] = {};
#pragma unroll 8
    for (int k = 0; k < 64; k++) {
        float a0 = sA[r0 * 65 + k];
        float a1 = sA[(r0 + 1) * 65 + k];
        float4 b = *reinterpret_cast<const float4*>(&sW[k * 64 + c0]);
        acc[0][0] += a0 * b.x; acc[0][1] += a0 * b.y; acc[0][2] += a0 * b.z; acc[0][3] += a0 * b.w;
        acc[1][0] += a1 * b.x; acc[1][1] += a1 * b.y; acc[1][2] += a1 * b.z; acc[1][3] += a1 * b.w;
    }
#pragma unroll
    for (int i = 0; i < 2; i++)
#pragma unroll
        for (int j = 0; j < 4; j++)
            g_h[(nb + r0 + i) * 64 + c0 + j] = acc[i][j] * 0.125f;
}

// ---------------- fused pre-split tf32 MLP + message + scatter ------------------
// 256 threads / 8 warps, 128 edges per CTA, warp owns 16 edges (one m16 tile).
// All operands pre-split to (hi,lo) uint2 pairs in smem; mainloop = LDS.64 + MMA.
// In-place bufA updates are fenced with __syncwarp() (read-all -> barrier -> write).
// Smem: [ W region 12544 uint2 | bufA 128x68 uint2 | bufB 128x72 f32 ] = 206,848 B
//   W region first holds W1@0 [8x68], W2@544 [64x68], W3@4896 [64x68];
//   after layer 3 it is overwritten by W4 [64x196].

__device__ __forceinline__ void mma_layer_ps(const uint2* __restrict__ A,
                                             const uint2* __restrict__ W, int ws,
                                             int nbase, float C[8][4],
                                             int w16, int lane) {
    const int row = lane >> 2, kq = lane & 3, bcol = lane >> 2;
#pragma unroll
    for (int nt = 0; nt < 8; nt++)
        C[nt][0] = C[nt][1] = C[nt][2] = C[nt][3] = 0.f;
#pragma unroll
    for (int kt = 0; kt < 8; kt++) {
        uint2 pa0 = A[(w16 + row)     * 68 + kt * 8 + kq];
        uint2 pa1 = A[(w16 + row + 8) * 68 + kt * 8 + kq];
        uint2 pa2 = A[(w16 + row)     * 68 + kt * 8 + 4 + kq];
        uint2 pa3 = A[(w16 + row + 8) * 68 + kt * 8 + 4 + kq];
#pragma unroll
        for (int nt = 0; nt < 8; nt++) {
            const int n = nbase + nt * 8 + bcol;
            uint2 b0 = W[(kt * 8 + kq)     * ws + n];
            uint2 b1 = W[(kt * 8 + 4 + kq) * ws + n];
            MMA8(C[nt], pa0.x, pa1.x, pa2.x, pa3.x, b0.x, b1.x);
            MMA8(C[nt], pa0.x, pa1.x, pa2.x, pa3.x, b0.y, b1.y);
            MMA8(C[nt], pa0.y, pa1.y, pa2.y, pa3.y, b0.x, b1.x);
        }
    }
}

// silu + split + store pairs into bufA. Caller must __syncwarp() between the
// preceding read of bufA and this write (in-place update).
__device__ __forceinline__ void store_act_split(uint2* __restrict__ bufA, float C[8][4],
                                                float scale, int w16, int lane) {
    const int row = lane >> 2, kq = lane & 3;
#pragma unroll
    for (int nt = 0; nt < 8; nt++) {
        float v0 = C[nt][0] * scale, v1 = C[nt][1] * scale;
        float v2 = C[nt][2] * scale, v3 = C[nt][3] * scale;
        v0 = __fdividef(v0, 1.f + __expf(-v0));
        v1 = __fdividef(v1, 1.f + __expf(-v1));
        v2 = __fdividef(v2, 1.f + __expf(-v2));
        v3 = __fdividef(v3, 1.f + __expf(-v3));
        const int col = nt * 8 + 2 * kq;
        uint2 p0 = split2(v0), p1 = split2(v1), p2 = split2(v2), p3 = split2(v3);
        *reinterpret_cast<uint4*>(&bufA[(w16 + row)     * 68 + col]) =
            make_uint4(p0.x, p0.y, p1.x, p1.y);
        *reinterpret_cast<uint4*>(&bufA[(w16 + row + 8) * 68 + col]) =
            make_uint4(p2.x, p2.y, p3.x, p3.y);
    }
}

__global__ void __launch_bounds__(256) k_fused(
    const float* __restrict__ radial, const float* __restrict__ vectors,
    const int* __restrict__ senders, const int* __restrict__ receivers,
    const float* __restrict__ w1, const float* __restrict__ w2,
    const float* __restrict__ w3, const float* __restrict__ w4) {
    extern __shared__ __align__(16) char smraw[];
    uint2* sW   = reinterpret_cast<uint2*>(smraw);            // 12544 uint2
    uint2* bufA = sW + 12544;                                 //  8704 uint2
    float* bufB = reinterpret_cast<float*>(bufA + 8704);      //  9216 f32

    const int t    = threadIdx.x;
    const int warp = t >> 5;
    const int lane = t & 31;
    const int w16  = warp * 16;
    const int row = lane >> 2, kq = lane & 3, bcol = lane >> 2;

    // ---- fill W1, W2, W3 (split once) ----
    for (int i = t; i < 512;  i += 256) sW[(i >> 6) * 68 + (i & 63)]        = split2(w1[i]);
    for (int i = t; i < 4096; i += 256) sW[544  + (i >> 6) * 68 + (i & 63)] = split2(w2[i]);
    for (int i = t; i < 4096; i += 256) sW[4896 + (i >> 6) * 68 + (i & 63)] = split2(w3[i]);
    __syncthreads();

    float C[8][4];

    // ---- layer 1: radial[16,8] @ W1, scale 1/sqrt(8), silu -> bufA ----
    {
        const float* rb = radial + (size_t)(blockIdx.x * 128 + w16) * 8;
        uint2 a0 = split2(rb[row * 8 + kq]);
        uint2 a1 = split2(rb[(row + 8) * 8 + kq]);
        uint2 a2 = split2(rb[row * 8 + 4 + kq]);
        uint2 a3 = split2(rb[(row + 8) * 8 + 4 + kq]);
#pragma unroll
        for (int nt = 0; nt < 8; nt++) {
            C[nt][0] = C[nt][1] = C[nt][2] = C[nt][3] = 0.f;
            const int n = nt * 8 + bcol;
            uint2 b0 = sW[kq * 68 + n];
            uint2 b1 = sW[(4 + kq) * 68 + n];
            MMA8(C[nt], a0.x, a1.x, a2.x, a3.x, b0.x, b1.x);
            MMA8(C[nt], a0.x, a1.x, a2.x, a3.x, b0.y, b1.y);
            MMA8(C[nt], a0.y, a1.y, a2.y, a3.y, b0.x, b1.x);
        }
        store_act_split(bufA, C, 0.35355339059327373f, w16, lane);
    }
    __syncwarp();

    // ---- layers 2, 3 (in-place on bufA; barrier between read and write) ----
    mma_layer_ps(bufA, sW + 544, 68, 0, C, w16, lane);
    __syncwarp();
    store_act_split(bufA, C, 0.125f, w16, lane);
    __syncwarp();
    mma_layer_ps(bufA, sW + 4896, 68, 0, C, w16, lane);
    __syncwarp();
    store_act_split(bufA, C, 0.125f, w16, lane);

    // ---- per-edge data (issue loads before the barrier to hide latency) ----
    const int  eloc = w16 + (lane >> 1);
    const int  e    = blockIdx.x * 128 + eloc;
    const int  half = lane & 1;
    const int  snd  = senders[e];
    const int  rcv  = receivers[e];
    float vx = vectors[(size_t)e * 3 + 0];
    float vy = vectors[(size_t)e * 3 + 1];
    float vz = vectors[(size_t)e * 3 + 2];

    __syncthreads();                       // all warps done reading W2/W3
    // ---- overwrite W region with W4 (split once) ----
    for (int i = t; i < 12288; i += 256) {
        int k = i / 192;
        sW[k * 196 + (i - k * 192)] = split2(w4[i]);
    }
    __syncthreads();

    const float* hrow = g_h + (size_t)snd * 64 + half * 32;
    float*       aggb = g_agg + (size_t)rcv * 576 + half * 32;
    float Y1[3], Y2[5];
    {
        float rn = rsqrtf(vx * vx + vy * vy + vz * vz);
        float x = vx * rn, y = vy * rn, z = vz * rn;
        const float SQ3 = 1.7320508075688772f, S15 = 3.872983346207417f;
        Y1[0] = SQ3 * x; Y1[1] = SQ3 * y; Y1[2] = SQ3 * z;
        Y2[0] = S15 * x * y; Y2[1] = S15 * y * z;
        Y2[2] = 1.118033988749895f * (3.f * z * z - 1.f);
        Y2[3] = S15 * x * z; Y2[4] = 0.5f * S15 * (x * x - y * y);
    }
    const float SCL = 0.0009765625f;   // 0.125 (w4 norm) * (1/64) * 0.5 (EPS)

    // ---- layer 4: 3 segments of 64 cols -> bufB -> message + red.v4 scatter ----
#pragma unroll
    for (int seg = 0; seg < 3; seg++) {
        mma_layer_ps(bufA, sW, 196, seg * 64, C, w16, lane);
        // plain f32 stage (no silu, no split); bufB writes race nothing (fresh buffer
        // per segment, fenced by the __syncwarp below before reads)
#pragma unroll
        for (int nt = 0; nt < 8; nt++) {
            const int col = nt * 8 + 2 * kq;
            *reinterpret_cast<float2*>(&bufB[(w16 + row)     * 72 + col]) =
                make_float2(C[nt][0], C[nt][1]);
            *reinterpret_cast<float2*>(&bufB[(w16 + row + 8) * 72 + col]) =
                make_float2(C[nt][2], C[nt][3]);
        }
        __syncwarp();

        const float* drow = bufB + eloc * 72 + half * 32;
        const int NP  = (seg == 0) ? 1 : (seg == 1 ? 3 : 5);
        const int OFF = (seg == 0) ? 0 : (seg == 1 ? 64 : 256);
        const float* Y = (seg == 1) ? Y1 : Y2;
#pragma unroll
        for (int c4 = 0; c4 < 8; c4++) {
            float4 d  = *reinterpret_cast<const float4*>(drow + c4 * 4);
            float4 h4 = *reinterpret_cast<const float4*>(hrow + c4 * 4);
            float u0 = d.x * h4.x * SCL;
            float u1 = d.y * h4.y * SCL;
            float u2 = d.z * h4.z * SCL;
            float u3 = d.w * h4.w * SCL;
            if (seg == 0) {
                red4(aggb + c4 * 4, u0, u1, u2, u3);
            } else {
#pragma unroll
                for (int p = 0; p < 5; p++) {
                    if (p < NP) {
                        float yp = Y[p];
                        red4(aggb + OFF + p * 64 + c4 * 4, u0 * yp, u1 * yp, u2 * yp, u3 * yp);
                    }
                }
            }
        }
        __syncwarp();   // bufB reused next segment
    }
}

// ---------------- kernel 4: down-projection, staged coalesced output ------------
// One block = 64 nodes, all 9 planes. Results staged in smem sO[64][576];
// final write is fully coalesced float4.
__global__ void __launch_bounds__(256) k_down(const float* __restrict__ w0,
                                              const float* __restrict__ w1,
                                              const float* __restrict__ w2,
                                              float* __restrict__ out) {
    extern __shared__ float dsm[];
    float* sW = dsm;            // 3 * 4096 = 12288
    float* sA = dsm + 12288;    // 64 * 65  =  4160
    float* sO = dsm + 16448;    // 64 * 576 = 36864   (total 53312 f = 213,248 B)

    const int t  = threadIdx.x;
    const int nb = blockIdx.x * 64;

    for (int i = t; i < 4096; i += 256) { sW[i] = w0[i]; sW[4096 + i] = w1[i]; sW[8192 + i] = w2[i]; }

    const int ty = t >> 4, tx = t & 15;
    const int r0 = ty * 4, d0 = tx * 4;

    for (int plane = 0; plane < 9; plane++) {
        const float* W; int roff, woff, stride;
        if (plane == 0)      { W = sW;        roff = 0;                     woff = 0;                 stride = 1; }
        else if (plane < 4)  { W = sW + 4096; roff = 64  + (plane - 1) * 64; woff = 64  + (plane - 1); stride = 3; }
        else                 { W = sW + 8192; roff = 256 + (plane - 4) * 64; woff = 256 + (plane - 4); stride = 5; }

        __syncthreads();   // prior plane's sA reads complete (also covers sW fill)
        for (int i = t; i < 4096; i += 256) {
            int rr = i >> 6, cc = i & 63;
            int n = nb + rr;
            sA[rr * 65 + cc] = (n < N_NODES) ? g_agg[(size_t)n * 576 + roff + cc] : 0.f;
        }
        __syncthreads();

        float acc[4][4] = {};
#pragma unroll 8
        for (int k = 0; k < 64; k++) {
            float a[4];
#pragma unroll
            for (int i = 0; i < 4; i++) a[i] = sA[(r0 + i) * 65 + k];
            float4 b = *reinterpret_cast<const float4*>(&W[k * 64 + d0]);
#pragma unroll
            for (int i = 0; i < 4; i++) {
                acc[i][0] += a[i] * b.x; acc[i][1] += a[i] * b.y;
                acc[i][2] += a[i] * b.z; acc[i][3] += a[i] * b.w;
            }
        }
#pragma unroll
        for (int i = 0; i < 4; i++)
#pragma unroll
            for (int j = 0; j < 4; j++)
                sO[(r0 + i) * 576 + woff + (d0 + j) * stride] = acc[i][j] * 0.125f;
    }
    __syncthreads();

    // coalesced float4 copy out (guard the ragged last block)
    const float4* s4 = reinterpret_cast<const float4*>(sO);
    float4*       o4 = reinterpret_cast<float4*>(out);
    for (int i = t; i < 64 * 144; i += 256) {
        int n = nb + i / 144;
        if (n < N_NODES) o4[(size_t)n * 144 + (i % 144)] = s4[i];
    }
}

// ---------------- launcher ------------------------------------------------------
extern "C" void kernel_launch(void* const* d_in, const int* in_sizes, int n_in,
                              void* d_out, int out_size) {
    const float* vectors    = (const float*)d_in[0];
    const float* node_feats = (const float*)d_in[1];
    const float* radial     = (const float*)d_in[2];
    const int*   senders    = (const int*)  d_in[3];
    const int*   receivers  = (const int*)  d_in[4];
    const float* w_up       = (const float*)d_in[5];
    const float* mlp_w1     = (const float*)d_in[6];
    const float* mlp_w2     = (const float*)d_in[7];
    const float* mlp_w3     = (const float*)d_in[8];
    const float* mlp_w4     = (const float*)d_in[9];
    const float* w_down0    = (const float*)d_in[10];
    const float* w_down1    = (const float*)d_in[11];
    const float* w_down2    = (const float*)d_in[12];
    float* out = (float*)d_out;

    const int FUSED_SMEM = 206848;
    const int DOWN_SMEM  = 213248;
    cudaFuncSetAttribute(k_fused, cudaFuncAttributeMaxDynamicSharedMemorySize, FUSED_SMEM);
    cudaFuncSetAttribute(k_down,  cudaFuncAttributeMaxDynamicSharedMemorySize, DOWN_SMEM);

    k_zero<<<11250, 256>>>();
    k_node_up<<<625, 256>>>(node_feats, w_up);
    k_fused<<<2500, 256, FUSED_SMEM>>>(radial, vectors, senders, receivers,
                                       mlp_w1, mlp_w2, mlp_w3, mlp_w4);
    k_down<<<313, 256, DOWN_SMEM>>>(w_down0, w_down1, w_down2, out);
}

// round 7
// speedup vs baseline: 1.6730x; 1.6730x over previous
#include <cuda_runtime.h>
#include <cstdint>

#define N_NODES 20000
#define N_EDGES 320000

typedef unsigned long long u64;

// ---------------- device scratch -----------------------------------------------
__device__ __align__(16) float g_h[N_NODES * 64];              // h = nf@w_up/8
__device__ __align__(16) float g_agg[(size_t)N_NODES * 576];   // m-major planes

// ---------------- helpers -------------------------------------------------------
__device__ __forceinline__ uint32_t packbf(float lo, float hi) {
    uint32_t d; asm("cvt.rn.bf16x2.f32 %0, %1, %2;" : "=r"(d) : "f"(hi), "f"(lo));
    return d;
}
// split (v0,v1) -> (hi bf16x2, lo bf16x2), v0 in low half
__device__ __forceinline__ uint2 split_pair(float v0, float v1) {
    uint32_t h = packbf(v0, v1);
    float l0 = v0 - __uint_as_float(h << 16);
    float l1 = v1 - __uint_as_float(h & 0xFFFF0000u);
    return make_uint2(h, packbf(l0, l1));
}
__device__ __forceinline__ void red4(float* p, float a, float b, float c, float d) {
    asm volatile("red.global.add.v4.f32 [%0], {%1, %2, %3, %4};"
                 :: "l"((u64)__cvta_generic_to_global(p)),
                    "f"(a), "f"(b), "f"(c), "f"(d) : "memory");
}
#define MMA16(C, a0, a1, a2, a3, b0, b1) \
    asm volatile("mma.sync.aligned.m16n8k16.row.col.f32.bf16.bf16.f32 " \
        "{%0,%1,%2,%3}, {%4,%5,%6,%7}, {%8,%9}, {%0,%1,%2,%3};" \
        : "+f"((C)[0]), "+f"((C)[1]), "+f"((C)[2]), "+f"((C)[3]) \
        : "r"(a0), "r"(a1), "r"(a2), "r"(a3), "r"(b0), "r"(b1))
#define MMA8B(C, a0, a1, b0) \
    asm volatile("mma.sync.aligned.m16n8k8.row.col.f32.bf16.bf16.f32 " \
        "{%0,%1,%2,%3}, {%4,%5}, {%6}, {%0,%1,%2,%3};" \
        : "+f"((C)[0]), "+f"((C)[1]), "+f"((C)[2]), "+f"((C)[3]) \
        : "r"(a0), "r"(a1), "r"(b0))

// ---------------- kernel 0: zero agg -------------------------------------------
__global__ void k_zero() {
    size_t i = (size_t)blockIdx.x * 256 + threadIdx.x;
    reinterpret_cast<float4*>(g_agg)[i] = make_float4(0.f, 0.f, 0.f, 0.f);
}

// ---------------- kernel 1: h = nf @ w_up * (1/8) -------------------------------
__global__ void __launch_bounds__(256) k_node_up(const float* __restrict__ nf,
                                                 const float* __restrict__ w) {
    __shared__ __align__(16) float sW[64 * 64];
    __shared__ float sA[32 * 65];
    const int t  = threadIdx.x;
    const int nb = blockIdx.x * 32;
    for (int i = t; i < 4096; i += 256) sW[i] = w[i];
    for (int i = t; i < 2048; i += 256) sA[(i >> 6) * 65 + (i & 63)] = nf[nb * 64 + i];
    __syncthreads();
    const int ty = t >> 4, tx = t & 15;
    const int r0 = ty * 2, c0 = tx * 4;
    float acc[2][4] = {};
#pragma unroll 8
    for (int k = 0; k < 64; k++) {
        float a0 = sA[r0 * 65 + k];
        float a1 = sA[(r0 + 1) * 65 + k];
        float4 b = *reinterpret_cast<const float4*>(&sW[k * 64 + c0]);
        acc[0][0] += a0 * b.x; acc[0][1] += a0 * b.y; acc[0][2] += a0 * b.z; acc[0][3] += a0 * b.w;
        acc[1][0] += a1 * b.x; acc[1][1] += a1 * b.y; acc[1][2] += a1 * b.z; acc[1][3] += a1 * b.w;
    }
#pragma unroll
    for (int i = 0; i < 2; i++)
#pragma unroll
        for (int j = 0; j < 4; j++)
            g_h[(nb + r0 + i) * 64 + c0 + j] = acc[i][j] * 0.125f;
}

// ---------------- fused bf16-split MMA MLP + message + scatter ------------------
// 256 threads / 8 warps, 128 edges/CTA, warp owns 16 edges (m16 tile, warp-local).
// Values x = hi + lo (bf16 each); D = Ah*Bh + Ah*Bl + Al*Bh  (err ~2^-16).
// Operands packed as bf16x2 along k (pairs 2k,2k+1). A stride 36 u32, W stride
// 72/200 u32 -> conflict-free fragment loads.
// Smem (u32 units): wHi1@0(288) wLo1@288 wHi2@576(2304) wLo2@2880 wHi3@5184
//   wLo3@7488 wHi4@9792(6400) wLo4@16192 aHi@22592(4608) aLo@27200 bufB@31808(9216)
//   total 41024 u32 = 164096 B.

__device__ __forceinline__ void mma_layer_bf(const uint32_t* __restrict__ aHi,
                                             const uint32_t* __restrict__ aLo,
                                             const uint32_t* __restrict__ wHi,
                                             const uint32_t* __restrict__ wLo,
                                             int ws, int nbase, float C[8][4],
                                             int w16, int lane) {
    const int row = lane >> 2, kq = lane & 3, bcol = lane >> 2;
#pragma unroll
    for (int nt = 0; nt < 8; nt++)
        C[nt][0] = C[nt][1] = C[nt][2] = C[nt][3] = 0.f;
#pragma unroll
    for (int kt = 0; kt < 4; kt++) {
        const int a0i = (w16 + row)     * 36 + kt * 8 + kq;
        const int a1i = (w16 + row + 8) * 36 + kt * 8 + kq;
        uint32_t ah0 = aHi[a0i],     al0 = aLo[a0i];
        uint32_t ah1 = aHi[a1i],     al1 = aLo[a1i];
        uint32_t ah2 = aHi[a0i + 4], al2 = aLo[a0i + 4];
        uint32_t ah3 = aHi[a1i + 4], al3 = aLo[a1i + 4];
        const int b0r = (kt * 8 + kq) * ws;
        const int b1r = (kt * 8 + 4 + kq) * ws;
#pragma unroll
        for (int nt = 0; nt < 8; nt++) {
            const int n = nbase + nt * 8 + bcol;
            uint32_t bh0 = wHi[b0r + n], bh1 = wHi[b1r + n];
            uint32_t bl0 = wLo[b0r + n], bl1 = wLo[b1r + n];
            MMA16(C[nt], ah0, ah1, ah2, ah3, bh0, bh1);
            MMA16(C[nt], ah0, ah1, ah2, ah3, bl0, bl1);
            MMA16(C[nt], al0, al1, al2, al3, bh0, bh1);
        }
    }
}

// silu + split + store packed pairs. Caller fences with __syncwarp() between the
// preceding read of aHi/aLo and this in-place write.
__device__ __forceinline__ void store_act_split(uint32_t* __restrict__ aHi,
                                                uint32_t* __restrict__ aLo,
                                                float C[8][4], float scale,
                                                int w16, int lane) {
    const int row = lane >> 2, kq = lane & 3;
#pragma unroll
    for (int nt = 0; nt < 8; nt++) {
        float v0 = C[nt][0] * scale, v1 = C[nt][1] * scale;
        float v2 = C[nt][2] * scale, v3 = C[nt][3] * scale;
        v0 = __fdividef(v0, 1.f + __expf(-v0));
        v1 = __fdividef(v1, 1.f + __expf(-v1));
        v2 = __fdividef(v2, 1.f + __expf(-v2));
        v3 = __fdividef(v3, 1.f + __expf(-v3));
        const int c01 = (w16 + row)     * 36 + nt * 4 + kq;
        const int c23 = (w16 + row + 8) * 36 + nt * 4 + kq;
        uint2 p01 = split_pair(v0, v1);
        uint2 p23 = split_pair(v2, v3);
        aHi[c01] = p01.x; aLo[c01] = p01.y;
        aHi[c23] = p23.x; aLo[c23] = p23.y;
    }
}

// cooperative weight split-fill: w[K][N] row-major -> packed k-pair arrays
__device__ __forceinline__ void fill_w(const float* __restrict__ w,
                                       uint32_t* __restrict__ dHi,
                                       uint32_t* __restrict__ dLo,
                                       int K2, int N, int ws, int t) {
    for (int i = t; i < K2 * N; i += 256) {
        int k2 = i / N, n = i - k2 * N;
        float v0 = w[(2 * k2) * N + n];
        float v1 = w[(2 * k2 + 1) * N + n];
        uint2 p = split_pair(v0, v1);
        dHi[k2 * ws + n] = p.x;
        dLo[k2 * ws + n] = p.y;
    }
}

__global__ void __launch_bounds__(256) k_fused(
    const float* __restrict__ radial, const float* __restrict__ vectors,
    const int* __restrict__ senders, const int* __restrict__ receivers,
    const float* __restrict__ w1, const float* __restrict__ w2,
    const float* __restrict__ w3, const float* __restrict__ w4) {
    extern __shared__ __align__(16) uint32_t smu[];
    uint32_t* wHi1 = smu;            uint32_t* wLo1 = smu + 288;
    uint32_t* wHi2 = smu + 576;      uint32_t* wLo2 = smu + 2880;
    uint32_t* wHi3 = smu + 5184;     uint32_t* wLo3 = smu + 7488;
    uint32_t* wHi4 = smu + 9792;     uint32_t* wLo4 = smu + 16192;
    uint32_t* aHi  = smu + 22592;    uint32_t* aLo  = smu + 27200;
    float*    bufB = reinterpret_cast<float*>(smu + 31808);   // 128 x 72 f32

    const int t    = threadIdx.x;
    const int warp = t >> 5;
    const int lane = t & 31;
    const int w16  = warp * 16;
    const int row = lane >> 2, kq = lane & 3, bcol = lane >> 2;

    fill_w(w1, wHi1, wLo1, 4,  64,  72,  t);
    fill_w(w2, wHi2, wLo2, 32, 64,  72,  t);
    fill_w(w3, wHi3, wLo3, 32, 64,  72,  t);
    fill_w(w4, wHi4, wLo4, 32, 192, 200, t);
    __syncthreads();

    float C[8][4];

    // ---- layer 1: radial[16,8] @ W1 (K=8, m16n8k8), scale 1/sqrt(8), silu ----
    {
        const float* rb = radial + (size_t)(blockIdx.x * 128 + w16) * 8;
        float2 q0 = *reinterpret_cast<const float2*>(rb + row * 8 + 2 * kq);
        float2 q1 = *reinterpret_cast<const float2*>(rb + (row + 8) * 8 + 2 * kq);
        uint2 a0 = split_pair(q0.x, q0.y);
        uint2 a1 = split_pair(q1.x, q1.y);
#pragma unroll
        for (int nt = 0; nt < 8; nt++) {
            C[nt][0] = C[nt][1] = C[nt][2] = C[nt][3] = 0.f;
            const int n = nt * 8 + bcol;
            uint32_t bh = wHi1[kq * 72 + n];
            uint32_t bl = wLo1[kq * 72 + n];
            MMA8B(C[nt], a0.x, a1.x, bh);
            MMA8B(C[nt], a0.x, a1.x, bl);
            MMA8B(C[nt], a0.y, a1.y, bh);
        }
        store_act_split(aHi, aLo, C, 0.35355339059327373f, w16, lane);
    }
    __syncwarp();

    // ---- layers 2, 3 (in-place on aHi/aLo; fence between read and write) ----
    mma_layer_bf(aHi, aLo, wHi2, wLo2, 72, 0, C, w16, lane);
    __syncwarp();
    store_act_split(aHi, aLo, C, 0.125f, w16, lane);
    __syncwarp();
    mma_layer_bf(aHi, aLo, wHi3, wLo3, 72, 0, C, w16, lane);
    __syncwarp();
    store_act_split(aHi, aLo, C, 0.125f, w16, lane);
    __syncwarp();

    // ---- per-edge data ----
    const int  eloc = w16 + (lane >> 1);
    const int  e    = blockIdx.x * 128 + eloc;
    const int  half = lane & 1;
    const int  snd  = senders[e];
    const int  rcv  = receivers[e];
    const float* hrow = g_h + (size_t)snd * 64 + half * 32;
    float*       aggb = g_agg + (size_t)rcv * 576 + half * 32;
    float Y1[3], Y2[5];
    {
        float vx = vectors[(size_t)e * 3 + 0];
        float vy = vectors[(size_t)e * 3 + 1];
        float vz = vectors[(size_t)e * 3 + 2];
        float rn = rsqrtf(vx * vx + vy * vy + vz * vz);
        float x = vx * rn, y = vy * rn, z = vz * rn;
        const float SQ3 = 1.7320508075688772f, S15 = 3.872983346207417f;
        Y1[0] = SQ3 * x; Y1[1] = SQ3 * y; Y1[2] = SQ3 * z;
        Y2[0] = S15 * x * y; Y2[1] = S15 * y * z;
        Y2[2] = 1.118033988749895f * (3.f * z * z - 1.f);
        Y2[3] = S15 * x * z; Y2[4] = 0.5f * S15 * (x * x - y * y);
    }
    const float SCL = 0.0009765625f;   // 0.125 (w4 norm) * (1/64) * 0.5 (EPS)

    // ---- layer 4: 3 segments of 64 cols -> bufB -> message + red.v4 scatter ----
#pragma unroll
    for (int seg = 0; seg < 3; seg++) {
        mma_layer_bf(aHi, aLo, wHi4, wLo4, 200, seg * 64, C, w16, lane);
#pragma unroll
        for (int nt = 0; nt < 8; nt++) {
            const int col = nt * 8 + 2 * kq;
            *reinterpret_cast<float2*>(&bufB[(w16 + row)     * 72 + col]) =
                make_float2(C[nt][0], C[nt][1]);
            *reinterpret_cast<float2*>(&bufB[(w16 + row + 8) * 72 + col]) =
                make_float2(C[nt][2], C[nt][3]);
        }
        __syncwarp();

        const float* drow = bufB + eloc * 72 + half * 32;
        const int NP  = (seg == 0) ? 1 : (seg == 1 ? 3 : 5);
        const int OFF = (seg == 0) ? 0 : (seg == 1 ? 64 : 256);
        const float* Y = (seg == 1) ? Y1 : Y2;
#pragma unroll
        for (int c4 = 0; c4 < 8; c4++) {
            float4 d  = *reinterpret_cast<const float4*>(drow + c4 * 4);
            float4 h4 = *reinterpret_cast<const float4*>(hrow + c4 * 4);
            float u0 = d.x * h4.x * SCL;
            float u1 = d.y * h4.y * SCL;
            float u2 = d.z * h4.z * SCL;
            float u3 = d.w * h4.w * SCL;
            if (seg == 0) {
                red4(aggb + c4 * 4, u0, u1, u2, u3);
            } else {
#pragma unroll
                for (int p = 0; p < 5; p++) {
                    if (p < NP) {
                        float yp = Y[p];
                        red4(aggb + OFF + p * 64 + c4 * 4, u0 * yp, u1 * yp, u2 * yp, u3 * yp);
                    }
                }
            }
        }
        __syncwarp();   // bufB reused next segment
    }
}

// ---------------- kernel 4: down-projection, 32-node tiles ----------------------
// grid (625, 3): x = node tile (32 nodes), y = l-group (l0 / l1 / l2).
// Streams the group's planes through one GEMM each, stages into sO, then a fully
// coalesced float4 writeback. 20000 = 625 * 32 exactly (no guards).
__global__ void __launch_bounds__(256) k_down(const float* __restrict__ w0,
                                              const float* __restrict__ w1,
                                              const float* __restrict__ w2,
                                              float* __restrict__ out) {
    extern __shared__ float dsm[];
    float* sW = dsm;           // 4096
    float* sA = dsm + 4096;    // 32 x 68 = 2176
    float* sO = dsm + 6272;    // up to 32 x 324 = 10368

    const int t   = threadIdx.x;
    const int nb  = blockIdx.x * 32;
    const int seg = blockIdx.y;
    const int nplanes = (seg == 0) ? 1 : (seg == 1 ? 3 : 5);
    const int stride  = nplanes;
    const int roff    = (seg == 0) ? 0 : (seg == 1 ? 64 : 256);     // agg col base
    const int ooff4   = (seg == 0) ? 0 : (seg == 1 ? 16 : 64);      // out float4 base
    const int ow      = 64 * stride;          // output cols this group
    const int rowp    = ow + 4;               // padded sO row (stays 16B-aligned)
    const float* W    = (seg == 0) ? w0 : (seg == 1 ? w1 : w2);

    for (int i = t; i < 4096; i += 256) sW[i] = W[i];

    const int ty = t >> 4, tx = t & 15;
    const int r0 = ty * 2, d0 = tx * 4;

    for (int p = 0; p < nplanes; p++) {
        __syncthreads();   // previous plane's sA reads complete (covers sW fill too)
        for (int i = t; i < 2048; i += 256) {
            int rr = i >> 6, cc = i & 63;
            sA[rr * 68 + cc] = g_agg[(size_t)(nb + rr) * 576 + roff + p * 64 + cc];
        }
        __syncthreads();

        float acc[2][4] = {};
#pragma unroll 8
        for (int k = 0; k < 64; k++) {
            float a0 = sA[r0 * 68 + k];
            float a1 = sA[(r0 + 1) * 68 + k];
            float4 b = *reinterpret_cast<const float4*>(&sW[k * 64 + d0]);
            acc[0][0] += a0 * b.x; acc[0][1] += a0 * b.y; acc[0][2] += a0 * b.z; acc[0][3] += a0 * b.w;
            acc[1][0] += a1 * b.x; acc[1][1] += a1 * b.y; acc[1][2] += a1 * b.z; acc[1][3] += a1 * b.w;
        }
#pragma unroll
        for (int i = 0; i < 2; i++)
#pragma unroll
            for (int j = 0; j < 4; j++)
                sO[(r0 + i) * rowp + (d0 + j) * stride + p] = acc[i][j] * 0.125f;
    }
    __syncthreads();

    // coalesced float4 writeback
    const int ow4 = ow >> 2, rowp4 = rowp >> 2;
    const float4* s4 = reinterpret_cast<const float4*>(sO);
    float4*       o4 = reinterpret_cast<float4*>(out);
    for (int i = t; i < 32 * ow4; i += 256) {
        int n = i / ow4, c = i - n * ow4;
        o4[(size_t)(nb + n) * 144 + ooff4 + c] = s4[n * rowp4 + c];
    }
}

// ---------------- launcher ------------------------------------------------------
extern "C" void kernel_launch(void* const* d_in, const int* in_sizes, int n_in,
                              void* d_out, int out_size) {
    const float* vectors    = (const float*)d_in[0];
    const float* node_feats = (const float*)d_in[1];
    const float* radial     = (const float*)d_in[2];
    const int*   senders    = (const int*)  d_in[3];
    const int*   receivers  = (const int*)  d_in[4];
    const float* w_up       = (const float*)d_in[5];
    const float* mlp_w1     = (const float*)d_in[6];
    const float* mlp_w2     = (const float*)d_in[7];
    const float* mlp_w3     = (const float*)d_in[8];
    const float* mlp_w4     = (const float*)d_in[9];
    const float* w_down0    = (const float*)d_in[10];
    const float* w_down1    = (const float*)d_in[11];
    const float* w_down2    = (const float*)d_in[12];
    float* out = (float*)d_out;

    const int FUSED_SMEM = 41024 * 4;    // 164096 B
    const int DOWN_SMEM  = 16640 * 4;    //  66560 B
    cudaFuncSetAttribute(k_fused, cudaFuncAttributeMaxDynamicSharedMemorySize, FUSED_SMEM);
    cudaFuncSetAttribute(k_down,  cudaFuncAttributeMaxDynamicSharedMemorySize, DOWN_SMEM);

    k_zero<<<11250, 256>>>();
    k_node_up<<<625, 256>>>(node_feats, w_up);
    k_fused<<<2500, 256, FUSED_SMEM>>>(radial, vectors, senders, receivers,
                                       mlp_w1, mlp_w2, mlp_w3, mlp_w4);
    k_down<<<dim3(625, 3), 256, DOWN_SMEM>>>(w_down0, w_down1, w_down2, out);
}

// round 8
// speedup vs baseline: 2.3195x; 1.3864x over previous
#include <cuda_runtime.h>
#include <cstdint>

#define N_NODES 20000
#define N_EDGES 320000

typedef unsigned long long u64;

// ---------------- device scratch -----------------------------------------------
__device__ __align__(16) float g_h[N_NODES * 64];              // h = nf@w_up/8
__device__ __align__(16) float g_agg[(size_t)N_NODES * 576];   // m-major planes
__device__ __align__(16) uint32_t g_wsplit[22592];             // pre-split weights

// ---------------- helpers -------------------------------------------------------
__device__ __forceinline__ uint32_t packbf(float lo, float hi) {
    uint32_t d; asm("cvt.rn.bf16x2.f32 %0, %1, %2;" : "=r"(d) : "f"(hi), "f"(lo));
    return d;
}
// split (v0,v1) -> (hi bf16x2, lo bf16x2), v0 in low half
__device__ __forceinline__ uint2 split_pair(float v0, float v1) {
    uint32_t h = packbf(v0, v1);
    float l0 = v0 - __uint_as_float(h << 16);
    float l1 = v1 - __uint_as_float(h & 0xFFFF0000u);
    return make_uint2(h, packbf(l0, l1));
}
__device__ __forceinline__ void red2(float* p, float a, float b) {
    asm volatile("red.global.add.v2.f32 [%0], {%1, %2};"
                 :: "l"((u64)__cvta_generic_to_global(p)), "f"(a), "f"(b) : "memory");
}
#define MMA16(C, a0, a1, a2, a3, b0, b1) \
    asm volatile("mma.sync.aligned.m16n8k16.row.col.f32.bf16.bf16.f32 " \
        "{%0,%1,%2,%3}, {%4,%5,%6,%7}, {%8,%9}, {%0,%1,%2,%3};" \
        : "+f"((C)[0]), "+f"((C)[1]), "+f"((C)[2]), "+f"((C)[3]) \
        : "r"(a0), "r"(a1), "r"(a2), "r"(a3), "r"(b0), "r"(b1))
#define MMA8B(C, a0, a1, b0) \
    asm volatile("mma.sync.aligned.m16n8k8.row.col.f32.bf16.bf16.f32 " \
        "{%0,%1,%2,%3}, {%4,%5}, {%6}, {%0,%1,%2,%3};" \
        : "+f"((C)[0]), "+f"((C)[1]), "+f"((C)[2]), "+f"((C)[3]) \
        : "r"(a0), "r"(a1), "r"(b0))

// ---------------- kernel P: pre-split all MLP weights (once, 4 blocks) ----------
// layout (u32): wHi1@0 [4x72]  wLo1@288   wHi2@576 [32x72]  wLo2@2880
//               wHi3@5184      wLo3@7488  wHi4@9792 [32x200] wLo4@16192
__device__ __forceinline__ void fill_dev(const float* __restrict__ w,
                                         uint32_t* __restrict__ dHi,
                                         uint32_t* __restrict__ dLo,
                                         int K2, int N, int ws, int t) {
    for (int i = t; i < K2 * N; i += 256) {
        int k2 = i / N, n = i - k2 * N;
        uint2 p = split_pair(w[(2 * k2) * N + n], w[(2 * k2 + 1) * N + n]);
        dHi[k2 * ws + n] = p.x;
        dLo[k2 * ws + n] = p.y;
    }
}
__global__ void __launch_bounds__(256) k_prep(const float* __restrict__ w1,
                                              const float* __restrict__ w2,
                                              const float* __restrict__ w3,
                                              const float* __restrict__ w4) {
    const int b = blockIdx.x, t = threadIdx.x;
    if (b == 0)      fill_dev(w1, g_wsplit,         g_wsplit + 288,   4,  64,  72,  t);
    else if (b == 1) fill_dev(w2, g_wsplit + 576,   g_wsplit + 2880,  32, 64,  72,  t);
    else if (b == 2) fill_dev(w3, g_wsplit + 5184,  g_wsplit + 7488,  32, 64,  72,  t);
    else             fill_dev(w4, g_wsplit + 9792,  g_wsplit + 16192, 32, 192, 200, t);
}

// ---------------- kernel 0: zero agg -------------------------------------------
__global__ void k_zero() {
    size_t i = (size_t)blockIdx.x * 256 + threadIdx.x;
    reinterpret_cast<float4*>(g_agg)[i] = make_float4(0.f, 0.f, 0.f, 0.f);
}

// ---------------- kernel 1: h = nf @ w_up * (1/8) -------------------------------
__global__ void __launch_bounds__(256) k_node_up(const float* __restrict__ nf,
                                                 const float* __restrict__ w) {
    __shared__ __align__(16) float sW[64 * 64];
    __shared__ float sA[32 * 65];
    const int t  = threadIdx.x;
    const int nb = blockIdx.x * 32;
    for (int i = t; i < 4096; i += 256) sW[i] = w[i];
    for (int i = t; i < 2048; i += 256) sA[(i >> 6) * 65 + (i & 63)] = nf[nb * 64 + i];
    __syncthreads();
    const int ty = t >> 4, tx = t & 15;
    const int r0 = ty * 2, c0 = tx * 4;
    float acc[2][4] = {};
#pragma unroll 8
    for (int k = 0; k < 64; k++) {
        float a0 = sA[r0 * 65 + k];
        float a1 = sA[(r0 + 1) * 65 + k];
        float4 b = *reinterpret_cast<const float4*>(&sW[k * 64 + c0]);
        acc[0][0] += a0 * b.x; acc[0][1] += a0 * b.y; acc[0][2] += a0 * b.z; acc[0][3] += a0 * b.w;
        acc[1][0] += a1 * b.x; acc[1][1] += a1 * b.y; acc[1][2] += a1 * b.z; acc[1][3] += a1 * b.w;
    }
#pragma unroll
    for (int i = 0; i < 2; i++)
#pragma unroll
        for (int j = 0; j < 4; j++)
            g_h[(nb + r0 + i) * 64 + c0 + j] = acc[i][j] * 0.125f;
}

// ---------------- fused bf16-split MMA MLP + fragment scatter -------------------
// 256 threads / 8 warps, 128 edges/CTA, warp owns 16 edges. 3-term bf16 split.
// Layer-4 results are scattered DIRECTLY from MMA fragments: lane (g,q) owns
// cols nt*8+2q(+1) of edges g and g+8 -> red.v2 per (edge, nt, plane).
// Smem (u32): weights@0 (22592, copied from g_wsplit) | aHi@22592 (4608) |
//             aLo@27200 (4608)  -> total 31808 u32 = 127,232 B.

__device__ __forceinline__ void mma_layer_bf(const uint32_t* __restrict__ aHi,
                                             const uint32_t* __restrict__ aLo,
                                             const uint32_t* __restrict__ wHi,
                                             const uint32_t* __restrict__ wLo,
                                             int ws, int nbase, float C[8][4],
                                             int w16, int lane) {
    const int row = lane >> 2, kq = lane & 3, bcol = lane >> 2;
#pragma unroll
    for (int nt = 0; nt < 8; nt++)
        C[nt][0] = C[nt][1] = C[nt][2] = C[nt][3] = 0.f;
#pragma unroll
    for (int kt = 0; kt < 4; kt++) {
        const int a0i = (w16 + row)     * 36 + kt * 8 + kq;
        const int a1i = (w16 + row + 8) * 36 + kt * 8 + kq;
        uint32_t ah0 = aHi[a0i],     al0 = aLo[a0i];
        uint32_t ah1 = aHi[a1i],     al1 = aLo[a1i];
        uint32_t ah2 = aHi[a0i + 4], al2 = aLo[a0i + 4];
        uint32_t ah3 = aHi[a1i + 4], al3 = aLo[a1i + 4];
        const int b0r = (kt * 8 + kq) * ws;
        const int b1r = (kt * 8 + 4 + kq) * ws;
#pragma unroll
        for (int nt = 0; nt < 8; nt++) {
            const int n = nbase + nt * 8 + bcol;
            uint32_t bh0 = wHi[b0r + n], bh1 = wHi[b1r + n];
            uint32_t bl0 = wLo[b0r + n], bl1 = wLo[b1r + n];
            MMA16(C[nt], ah0, ah1, ah2, ah3, bh0, bh1);
            MMA16(C[nt], ah0, ah1, ah2, ah3, bl0, bl1);
            MMA16(C[nt], al0, al1, al2, al3, bh0, bh1);
        }
    }
}

// silu + split + store packed pairs (in-place; caller fences with __syncwarp)
__device__ __forceinline__ void store_act_split(uint32_t* __restrict__ aHi,
                                                uint32_t* __restrict__ aLo,
                                                float C[8][4], float scale,
                                                int w16, int lane) {
    const int row = lane >> 2, kq = lane & 3;
#pragma unroll
    for (int nt = 0; nt < 8; nt++) {
        float v0 = C[nt][0] * scale, v1 = C[nt][1] * scale;
        float v2 = C[nt][2] * scale, v3 = C[nt][3] * scale;
        v0 = __fdividef(v0, 1.f + __expf(-v0));
        v1 = __fdividef(v1, 1.f + __expf(-v1));
        v2 = __fdividef(v2, 1.f + __expf(-v2));
        v3 = __fdividef(v3, 1.f + __expf(-v3));
        const int c01 = (w16 + row)     * 36 + nt * 4 + kq;
        const int c23 = (w16 + row + 8) * 36 + nt * 4 + kq;
        uint2 p01 = split_pair(v0, v1);
        uint2 p23 = split_pair(v2, v3);
        aHi[c01] = p01.x; aLo[c01] = p01.y;
        aHi[c23] = p23.x; aLo[c23] = p23.y;
    }
}

__device__ __forceinline__ void sh_of(const float* __restrict__ vectors, int e,
                                      float* y1v, float* y2v) {
    float vx = vectors[(size_t)e * 3 + 0];
    float vy = vectors[(size_t)e * 3 + 1];
    float vz = vectors[(size_t)e * 3 + 2];
    float rn = rsqrtf(vx * vx + vy * vy + vz * vz);
    float x = vx * rn, y = vy * rn, z = vz * rn;
    const float SQ3 = 1.7320508075688772f, S15 = 3.872983346207417f;
    y1v[0] = SQ3 * x; y1v[1] = SQ3 * y; y1v[2] = SQ3 * z;
    y2v[0] = S15 * x * y; y2v[1] = S15 * y * z;
    y2v[2] = 1.118033988749895f * (3.f * z * z - 1.f);
    y2v[3] = S15 * x * z; y2v[4] = 0.5f * S15 * (x * x - y * y);
}

__global__ void __launch_bounds__(256) k_fused(
    const float* __restrict__ radial, const float* __restrict__ vectors,
    const int* __restrict__ senders, const int* __restrict__ receivers) {
    extern __shared__ __align__(16) uint32_t smu[];
    uint32_t* wHi1 = smu;            uint32_t* wLo1 = smu + 288;
    uint32_t* wHi2 = smu + 576;      uint32_t* wLo2 = smu + 2880;
    uint32_t* wHi3 = smu + 5184;     uint32_t* wLo3 = smu + 7488;
    uint32_t* wHi4 = smu + 9792;     uint32_t* wLo4 = smu + 16192;
    uint32_t* aHi  = smu + 22592;    uint32_t* aLo  = smu + 27200;

    const int t    = threadIdx.x;
    const int warp = t >> 5;
    const int lane = t & 31;
    const int w16  = warp * 16;
    const int g = lane >> 2, q = lane & 3;

    // flat copy of pre-split weights (22592 u32 = 5648 uint4)
    {
        const uint4* src = reinterpret_cast<const uint4*>(g_wsplit);
        uint4*       dst = reinterpret_cast<uint4*>(smu);
        for (int i = t; i < 5648; i += 256) dst[i] = src[i];
    }
    __syncthreads();

    float C[8][4];

    // ---- layer 1: radial[16,8] @ W1 (K=8, m16n8k8), scale 1/sqrt(8), silu ----
    {
        const float* rb = radial + (size_t)(blockIdx.x * 128 + w16) * 8;
        float2 q0 = *reinterpret_cast<const float2*>(rb + g * 8 + 2 * q);
        float2 q1 = *reinterpret_cast<const float2*>(rb + (g + 8) * 8 + 2 * q);
        uint2 a0 = split_pair(q0.x, q0.y);
        uint2 a1 = split_pair(q1.x, q1.y);
#pragma unroll
        for (int nt = 0; nt < 8; nt++) {
            C[nt][0] = C[nt][1] = C[nt][2] = C[nt][3] = 0.f;
            const int n = nt * 8 + g;
            uint32_t bh = wHi1[q * 72 + n];
            uint32_t bl = wLo1[q * 72 + n];
            MMA8B(C[nt], a0.x, a1.x, bh);
            MMA8B(C[nt], a0.x, a1.x, bl);
            MMA8B(C[nt], a0.y, a1.y, bh);
        }
        store_act_split(aHi, aLo, C, 0.35355339059327373f, w16, lane);
    }
    __syncwarp();

    // ---- layers 2, 3 (in-place; fence read->write) ----
    mma_layer_bf(aHi, aLo, wHi2, wLo2, 72, 0, C, w16, lane);
    __syncwarp();
    store_act_split(aHi, aLo, C, 0.125f, w16, lane);
    __syncwarp();
    mma_layer_bf(aHi, aLo, wHi3, wLo3, 72, 0, C, w16, lane);
    __syncwarp();
    store_act_split(aHi, aLo, C, 0.125f, w16, lane);
    __syncwarp();

    // ---- per-lane edge data: lane (g,q) owns cols nt*8+2q of edges g, g+8 ----
    const int e0 = blockIdx.x * 128 + w16 + g;
    const int e1 = e0 + 8;
    const int snd0 = senders[e0],   snd1 = senders[e1];
    float* aggA = g_agg + (size_t)receivers[e0] * 576;
    float* aggB = g_agg + (size_t)receivers[e1] * 576;
    float y1a[3], y2a[5], y1b[3], y2b[5];
    sh_of(vectors, e0, y1a, y2a);
    sh_of(vectors, e1, y1b, y2b);
    const float SCL = 0.0009765625f;   // 0.125 (w4 norm) * (1/64) * 0.5 (EPS)

    // preload h pairs for this lane's columns (nt*8+2q, +1), both edges
    float2 hA[8], hB[8];
#pragma unroll
    for (int nt = 0; nt < 8; nt++) {
        hA[nt] = *reinterpret_cast<const float2*>(g_h + (size_t)snd0 * 64 + nt * 8 + 2 * q);
        hB[nt] = *reinterpret_cast<const float2*>(g_h + (size_t)snd1 * 64 + nt * 8 + 2 * q);
    }

    // ---- layer 4: 3 segments, scatter directly from fragments ----
#pragma unroll
    for (int seg = 0; seg < 3; seg++) {
        mma_layer_bf(aHi, aLo, wHi4, wLo4, 200, seg * 64, C, w16, lane);
        const int NP  = (seg == 0) ? 1 : (seg == 1 ? 3 : 5);
        const int OFF = (seg == 0) ? 0 : (seg == 1 ? 64 : 256);
        const float* Ya = (seg == 1) ? y1a : y2a;
        const float* Yb = (seg == 1) ? y1b : y2b;
#pragma unroll
        for (int nt = 0; nt < 8; nt++) {
            const int col = nt * 8 + 2 * q;
            float uA0 = C[nt][0] * hA[nt].x * SCL;
            float uA1 = C[nt][1] * hA[nt].y * SCL;
            float uB0 = C[nt][2] * hB[nt].x * SCL;
            float uB1 = C[nt][3] * hB[nt].y * SCL;
            if (seg == 0) {
                red2(aggA + col, uA0, uA1);
                red2(aggB + col, uB0, uB1);
            } else {
#pragma unroll
                for (int p = 0; p < 5; p++) {
                    if (p < NP) {
                        red2(aggA + OFF + p * 64 + col, uA0 * Ya[p], uA1 * Ya[p]);
                        red2(aggB + OFF + p * 64 + col, uB0 * Yb[p], uB1 * Yb[p]);
                    }
                }
            }
        }
    }
}

// ---------------- kernel 4: down-projection, pipelined planes -------------------
// grid (625, 3): x = 32-node tile, y = l-group. Double-buffered sA: next plane's
// global loads issue before the current GEMM. Coalesced float4 writeback.
__global__ void __launch_bounds__(256) k_down(const float* __restrict__ w0,
                                              const float* __restrict__ w1,
                                              const float* __restrict__ w2,
                                              float* __restrict__ out) {
    extern __shared__ float dsm[];
    float* sW    = dsm;            // 4096
    float* sAbuf = dsm + 4096;     // 2 x 2176
    float* sO    = dsm + 8448;     // up to 32 x 324 = 10368  (total 75,264 B)

    const int t   = threadIdx.x;
    const int nb  = blockIdx.x * 32;
    const int seg = blockIdx.y;
    const int nplanes = (seg == 0) ? 1 : (seg == 1 ? 3 : 5);
    const int stride  = nplanes;
    const int roff    = (seg == 0) ? 0 : (seg == 1 ? 64 : 256);
    const int ooff4   = (seg == 0) ? 0 : (seg == 1 ? 16 : 64);
    const int ow      = 64 * stride;
    const int rowp    = ow + 4;
    const float* W    = (seg == 0) ? w0 : (seg == 1 ? w1 : w2);

    for (int i = t; i < 4096; i += 256) sW[i] = W[i];

    const int ty = t >> 4, tx = t & 15;
    const int r0 = ty * 2, d0 = tx * 4;

    float rg[8];
#pragma unroll
    for (int j = 0; j < 8; j++) {
        int i = t + j * 256;
        rg[j] = g_agg[(size_t)(nb + (i >> 6)) * 576 + roff + (i & 63)];
    }

    for (int p = 0; p < nplanes; p++) {
        float* sA = sAbuf + (p & 1) * 2176;
#pragma unroll
        for (int j = 0; j < 8; j++) {
            int i = t + j * 256;
            sA[(i >> 6) * 68 + (i & 63)] = rg[j];
        }
        __syncthreads();
        if (p + 1 < nplanes) {
#pragma unroll
            for (int j = 0; j < 8; j++) {
                int i = t + j * 256;
                rg[j] = g_agg[(size_t)(nb + (i >> 6)) * 576 + roff + (p + 1) * 64 + (i & 63)];
            }
        }

        float acc[2][4] = {};
#pragma unroll 8
        for (int k = 0; k < 64; k++) {
            float a0 = sA[r0 * 68 + k];
            float a1 = sA[(r0 + 1) * 68 + k];
            float4 b = *reinterpret_cast<const float4*>(&sW[k * 64 + d0]);
            acc[0][0] += a0 * b.x; acc[0][1] += a0 * b.y; acc[0][2] += a0 * b.z; acc[0][3] += a0 * b.w;
            acc[1][0] += a1 * b.x; acc[1][1] += a1 * b.y; acc[1][2] += a1 * b.z; acc[1][3] += a1 * b.w;
        }
#pragma unroll
        for (int i = 0; i < 2; i++)
#pragma unroll
            for (int j = 0; j < 4; j++)
                sO[(r0 + i) * rowp + (d0 + j) * stride + p] = acc[i][j] * 0.125f;
    }
    __syncthreads();

    const int ow4 = ow >> 2, rowp4 = rowp >> 2;
    const float4* s4 = reinterpret_cast<const float4*>(sO);
    float4*       o4 = reinterpret_cast<float4*>(out);
    for (int i = t; i < 32 * ow4; i += 256) {
        int n = i / ow4, c = i - n * ow4;
        o4[(size_t)(nb + n) * 144 + ooff4 + c] = s4[n * rowp4 + c];
    }
}

// ---------------- launcher ------------------------------------------------------
extern "C" void kernel_launch(void* const* d_in, const int* in_sizes, int n_in,
                              void* d_out, int out_size) {
    const float* vectors    = (const float*)d_in[0];
    const float* node_feats = (const float*)d_in[1];
    const float* radial     = (const float*)d_in[2];
    const int*   senders    = (const int*)  d_in[3];
    const int*   receivers  = (const int*)  d_in[4];
    const float* w_up       = (const float*)d_in[5];
    const float* mlp_w1     = (const float*)d_in[6];
    const float* mlp_w2     = (const float*)d_in[7];
    const float* mlp_w3     = (const float*)d_in[8];
    const float* mlp_w4     = (const float*)d_in[9];
    const float* w_down0    = (const float*)d_in[10];
    const float* w_down1    = (const float*)d_in[11];
    const float* w_down2    = (const float*)d_in[12];
    float* out = (float*)d_out;

    const int FUSED_SMEM = 31808 * 4;    // 127,232 B
    const int DOWN_SMEM  = 18816 * 4;    //  75,264 B
    cudaFuncSetAttribute(k_fused, cudaFuncAttributeMaxDynamicSharedMemorySize, FUSED_SMEM);
    cudaFuncSetAttribute(k_down,  cudaFuncAttributeMaxDynamicSharedMemorySize, DOWN_SMEM);

    k_prep<<<4, 256>>>(mlp_w1, mlp_w2, mlp_w3, mlp_w4);
    k_zero<<<11250, 256>>>();
    k_node_up<<<625, 256>>>(node_feats, w_up);
    k_fused<<<2500, 256, FUSED_SMEM>>>(radial, vectors, senders, receivers);
    k_down<<<dim3(625, 3), 256, DOWN_SMEM>>>(w_down0, w_down1, w_down2, out);
}

// round 9
// speedup vs baseline: 2.9902x; 1.2891x over previous
#include <cuda_runtime.h>
#include <cstdint>

#define N_NODES 20000
#define N_EDGES 320000

typedef unsigned long long u64;

// ---------------- device scratch -----------------------------------------------
__device__ __align__(16) float g_h[N_NODES * 64];              // h = nf@w_up/8
__device__ __align__(16) float g_agg[(size_t)N_NODES * 576];   // m-major planes
__device__ __align__(16) uint32_t g_wsplit[22592];             // pre-split weights

// ---------------- helpers -------------------------------------------------------
__device__ __forceinline__ uint32_t packbf(float lo, float hi) {
    uint32_t d; asm("cvt.rn.bf16x2.f32 %0, %1, %2;" : "=r"(d) : "f"(hi), "f"(lo));
    return d;
}
// split (v0,v1) -> (hi bf16x2, lo bf16x2), v0 in low half
__device__ __forceinline__ uint2 split_pair(float v0, float v1) {
    uint32_t h = packbf(v0, v1);
    float l0 = v0 - __uint_as_float(h << 16);
    float l1 = v1 - __uint_as_float(h & 0xFFFF0000u);
    return make_uint2(h, packbf(l0, l1));
}
__device__ __forceinline__ void red4(float* p, float a, float b, float c, float d) {
    asm volatile("red.global.add.v4.f32 [%0], {%1, %2, %3, %4};"
                 :: "l"((u64)__cvta_generic_to_global(p)),
                    "f"(a), "f"(b), "f"(c), "f"(d) : "memory");
}
#define MMA16(C, a0, a1, a2, a3, b0, b1) \
    asm volatile("mma.sync.aligned.m16n8k16.row.col.f32.bf16.bf16.f32 " \
        "{%0,%1,%2,%3}, {%4,%5,%6,%7}, {%8,%9}, {%0,%1,%2,%3};" \
        : "+f"((C)[0]), "+f"((C)[1]), "+f"((C)[2]), "+f"((C)[3]) \
        : "r"(a0), "r"(a1), "r"(a2), "r"(a3), "r"(b0), "r"(b1))
#define MMA8B(C, a0, a1, b0) \
    asm volatile("mma.sync.aligned.m16n8k8.row.col.f32.bf16.bf16.f32 " \
        "{%0,%1,%2,%3}, {%4,%5}, {%6}, {%0,%1,%2,%3};" \
        : "+f"((C)[0]), "+f"((C)[1]), "+f"((C)[2]), "+f"((C)[3]) \
        : "r"(a0), "r"(a1), "r"(b0))

// ---------------- merged init kernel: zero agg + node_up + weight prep ----------
// blocks [0,11250): zero g_agg; [11250,11875): node_up (32 nodes each); [11875,11879): prep
__device__ __forceinline__ void fill_dev(const float* __restrict__ w,
                                         uint32_t* __restrict__ dHi,
                                         uint32_t* __restrict__ dLo,
                                         int K2, int N, int ws, int t) {
    for (int i = t; i < K2 * N; i += 256) {
        int k2 = i / N, n = i - k2 * N;
        uint2 p = split_pair(w[(2 * k2) * N + n], w[(2 * k2 + 1) * N + n]);
        dHi[k2 * ws + n] = p.x;
        dLo[k2 * ws + n] = p.y;
    }
}

__global__ void __launch_bounds__(256) k_init(
    const float* __restrict__ nf, const float* __restrict__ wup,
    const float* __restrict__ w1, const float* __restrict__ w2,
    const float* __restrict__ w3, const float* __restrict__ w4) {
    __shared__ __align__(16) float sW[64 * 64];
    __shared__ float sA[32 * 65];
    const int b = blockIdx.x;
    const int t = threadIdx.x;

    if (b < 11250) {                       // zero 46MB of g_agg
        size_t i = (size_t)b * 256 + t;
        reinterpret_cast<float4*>(g_agg)[i] = make_float4(0.f, 0.f, 0.f, 0.f);
    } else if (b < 11875) {                // h = nf @ w_up * (1/8)
        const int nb = (b - 11250) * 32;
        for (int i = t; i < 4096; i += 256) sW[i] = wup[i];
        for (int i = t; i < 2048; i += 256) sA[(i >> 6) * 65 + (i & 63)] = nf[nb * 64 + i];
        __syncthreads();
        const int ty = t >> 4, tx = t & 15;
        const int r0 = ty * 2, c0 = tx * 4;
        float acc[2][4] = {};
#pragma unroll 8
        for (int k = 0; k < 64; k++) {
            float a0 = sA[r0 * 65 + k];
            float a1 = sA[(r0 + 1) * 65 + k];
            float4 bb = *reinterpret_cast<const float4*>(&sW[k * 64 + c0]);
            acc[0][0] += a0 * bb.x; acc[0][1] += a0 * bb.y; acc[0][2] += a0 * bb.z; acc[0][3] += a0 * bb.w;
            acc[1][0] += a1 * bb.x; acc[1][1] += a1 * bb.y; acc[1][2] += a1 * bb.z; acc[1][3] += a1 * bb.w;
        }
#pragma unroll
        for (int i = 0; i < 2; i++)
#pragma unroll
            for (int j = 0; j < 4; j++)
                g_h[(nb + r0 + i) * 64 + c0 + j] = acc[i][j] * 0.125f;
    } else {                               // pre-split MLP weights
        const int bb = b - 11875;
        if (bb == 0)      fill_dev(w1, g_wsplit,        g_wsplit + 288,   4,  64,  72,  t);
        else if (bb == 1) fill_dev(w2, g_wsplit + 576,  g_wsplit + 2880,  32, 64,  72,  t);
        else if (bb == 2) fill_dev(w3, g_wsplit + 5184, g_wsplit + 7488,  32, 64,  72,  t);
        else              fill_dev(w4, g_wsplit + 9792, g_wsplit + 16192, 32, 192, 200, t);
    }
}

// ---------------- fused register-dataflow bf16-split MLP + scatter --------------
// 256 threads / 8 warps, 128 edges/CTA, warp owns 16 edges (one m16 tile).
// KEY: m16n8k16 C-fragment layout == next layer's A-fragment layout, so
// activations stay in registers (silu + split in-regs); smem holds ONLY weights
// (22592 u32 = 90,368 B -> 2 CTAs/SM).  3-term bf16 split: D = AhBh + AhBl + AlBh.

__device__ __forceinline__ void mma_layer_reg(const uint32_t* __restrict__ aH,
                                              const uint32_t* __restrict__ aL,
                                              const uint32_t* __restrict__ wHi,
                                              const uint32_t* __restrict__ wLo,
                                              int ws, int nbase, float C[8][4],
                                              int lane) {
    const int g = lane >> 2, q = lane & 3;
#pragma unroll
    for (int nt = 0; nt < 8; nt++)
        C[nt][0] = C[nt][1] = C[nt][2] = C[nt][3] = 0.f;
#pragma unroll
    for (int kt = 0; kt < 4; kt++) {
        uint32_t ah0 = aH[kt * 4 + 0], ah1 = aH[kt * 4 + 1];
        uint32_t ah2 = aH[kt * 4 + 2], ah3 = aH[kt * 4 + 3];
        uint32_t al0 = aL[kt * 4 + 0], al1 = aL[kt * 4 + 1];
        uint32_t al2 = aL[kt * 4 + 2], al3 = aL[kt * 4 + 3];
        const int b0r = (kt * 8 + q) * ws;
        const int b1r = (kt * 8 + 4 + q) * ws;
#pragma unroll
        for (int nt = 0; nt < 8; nt++) {
            const int n = nbase + nt * 8 + g;
            uint32_t bh0 = wHi[b0r + n], bh1 = wHi[b1r + n];
            uint32_t bl0 = wLo[b0r + n], bl1 = wLo[b1r + n];
            MMA16(C[nt], ah0, ah1, ah2, ah3, bh0, bh1);
            MMA16(C[nt], ah0, ah1, ah2, ah3, bl0, bl1);
            MMA16(C[nt], al0, al1, al2, al3, bh0, bh1);
        }
    }
}

// silu(scale*C) -> bf16 hi/lo A-fragments, all in registers.
// A-frag k-tile kt <- C tiles nt=2kt (cols k=16kt+2q,+1) and nt=2kt+1 (k+8).
__device__ __forceinline__ void act_frags(const float C[8][4], float scale,
                                          uint32_t* __restrict__ aH,
                                          uint32_t* __restrict__ aL) {
    float v[8][4];
#pragma unroll
    for (int nt = 0; nt < 8; nt++)
#pragma unroll
        for (int j = 0; j < 4; j++) {
            float x = C[nt][j] * scale;
            v[nt][j] = __fdividef(x, 1.f + __expf(-x));
        }
#pragma unroll
    for (int kt = 0; kt < 4; kt++) {
        uint2 p0 = split_pair(v[2 * kt][0],     v[2 * kt][1]);      // row g,   k..k+1
        uint2 p1 = split_pair(v[2 * kt][2],     v[2 * kt][3]);      // row g+8
        uint2 p2 = split_pair(v[2 * kt + 1][0], v[2 * kt + 1][1]);  // row g,   k+8..k+9
        uint2 p3 = split_pair(v[2 * kt + 1][2], v[2 * kt + 1][3]);  // row g+8
        aH[kt * 4 + 0] = p0.x; aL[kt * 4 + 0] = p0.y;
        aH[kt * 4 + 1] = p1.x; aL[kt * 4 + 1] = p1.y;
        aH[kt * 4 + 2] = p2.x; aL[kt * 4 + 2] = p2.y;
        aH[kt * 4 + 3] = p3.x; aL[kt * 4 + 3] = p3.y;
    }
}

__device__ __forceinline__ void sh_of(const float* __restrict__ vectors, int e,
                                      float* y1v, float* y2v) {
    float vx = vectors[(size_t)e * 3 + 0];
    float vy = vectors[(size_t)e * 3 + 1];
    float vz = vectors[(size_t)e * 3 + 2];
    float rn = rsqrtf(vx * vx + vy * vy + vz * vz);
    float x = vx * rn, y = vy * rn, z = vz * rn;
    const float SQ3 = 1.7320508075688772f, S15 = 3.872983346207417f;
    y1v[0] = SQ3 * x; y1v[1] = SQ3 * y; y1v[2] = SQ3 * z;
    y2v[0] = S15 * x * y; y2v[1] = S15 * y * z;
    y2v[2] = 1.118033988749895f * (3.f * z * z - 1.f);
    y2v[3] = S15 * x * z; y2v[4] = 0.5f * S15 * (x * x - y * y);
}

__global__ void __launch_bounds__(256, 2) k_fused(
    const float* __restrict__ radial, const float* __restrict__ vectors,
    const int* __restrict__ senders, const int* __restrict__ receivers) {
    extern __shared__ __align__(16) uint32_t smu[];
    uint32_t* wHi1 = smu;            uint32_t* wLo1 = smu + 288;
    uint32_t* wHi2 = smu + 576;      uint32_t* wLo2 = smu + 2880;
    uint32_t* wHi3 = smu + 5184;     uint32_t* wLo3 = smu + 7488;
    uint32_t* wHi4 = smu + 9792;     uint32_t* wLo4 = smu + 16192;

    const int t    = threadIdx.x;
    const int warp = t >> 5;
    const int lane = t & 31;
    const int w16  = warp * 16;
    const int g = lane >> 2, q = lane & 3;

    // flat copy of pre-split weights (22592 u32 = 5648 uint4)
    {
        const uint4* src = reinterpret_cast<const uint4*>(g_wsplit);
        uint4*       dst = reinterpret_cast<uint4*>(smu);
        for (int i = t; i < 5648; i += 256) dst[i] = src[i];
    }
    __syncthreads();

    float C[8][4];
    uint32_t aH[16], aL[16];

    // ---- layer 1: radial[16,8] @ W1 (m16n8k8), scale 1/sqrt(8), silu ----
    {
        const float* rb = radial + (size_t)(blockIdx.x * 128 + w16) * 8;
        float2 q0 = *reinterpret_cast<const float2*>(rb + g * 8 + 2 * q);
        float2 q1 = *reinterpret_cast<const float2*>(rb + (g + 8) * 8 + 2 * q);
        uint2 a0 = split_pair(q0.x, q0.y);
        uint2 a1 = split_pair(q1.x, q1.y);
#pragma unroll
        for (int nt = 0; nt < 8; nt++) {
            C[nt][0] = C[nt][1] = C[nt][2] = C[nt][3] = 0.f;
            const int n = nt * 8 + g;
            uint32_t bh = wHi1[q * 72 + n];
            uint32_t bl = wLo1[q * 72 + n];
            MMA8B(C[nt], a0.x, a1.x, bh);
            MMA8B(C[nt], a0.x, a1.x, bl);
            MMA8B(C[nt], a0.y, a1.y, bh);
        }
        act_frags(C, 0.35355339059327373f, aH, aL);
    }

    // ---- layers 2, 3: pure register dataflow, no smem, no syncs ----
    mma_layer_reg(aH, aL, wHi2, wLo2, 72, 0, C, lane);
    act_frags(C, 0.125f, aH, aL);
    mma_layer_reg(aH, aL, wHi3, wLo3, 72, 0, C, lane);
    act_frags(C, 0.125f, aH, aL);

    // ---- per-lane edge data (all q lanes of a g share edges e0, e1) ----
    const int e0 = blockIdx.x * 128 + w16 + g;
    const int e1 = e0 + 8;
    const int snd0 = senders[e0], snd1 = senders[e1];
    float* aggA = g_agg + (size_t)receivers[e0] * 576;
    float* aggB = g_agg + (size_t)receivers[e1] * 576;
    float y1a[3], y2a[5], y1b[3], y2b[5];
    sh_of(vectors, e0, y1a, y2a);
    sh_of(vectors, e1, y1b, y2b);
    const float SCL = 0.0009765625f;   // 0.125 (w4 norm) * (1/64) * 0.5 (EPS)

    float2 hA[8], hB[8];
#pragma unroll
    for (int nt = 0; nt < 8; nt++) {
        hA[nt] = *reinterpret_cast<const float2*>(g_h + (size_t)snd0 * 64 + nt * 8 + 2 * q);
        hB[nt] = *reinterpret_cast<const float2*>(g_h + (size_t)snd1 * 64 + nt * 8 + 2 * q);
    }

    const bool odd  = (q & 1);
    const int  col4 = (q >> 1) * 4;     // this lane's 4-col block base within nt*8
    float*       myAgg = odd ? aggB : aggA;

    // ---- layer 4: 3 segments, scatter via lane-pair exchange + red.v4 ----
#pragma unroll
    for (int seg = 0; seg < 3; seg++) {
        mma_layer_reg(aH, aL, wHi4, wLo4, 200, seg * 64, C, lane);
        const int NP  = (seg == 0) ? 1 : (seg == 1 ? 3 : 5);
        const int OFF = (seg == 0) ? 0 : (seg == 1 ? 64 : 256);
        const float* Yv = odd ? ((seg == 1) ? y1b : y2b) : ((seg == 1) ? y1a : y2a);
#pragma unroll
        for (int nt = 0; nt < 8; nt++) {
            float uA0 = C[nt][0] * hA[nt].x * SCL;
            float uA1 = C[nt][1] * hA[nt].y * SCL;
            float uB0 = C[nt][2] * hB[nt].x * SCL;
            float uB1 = C[nt][3] * hB[nt].y * SCL;
            // lane-pair exchange: even lane collects edge-A (4 cols), odd edge-B
            float s0 = odd ? uA0 : uB0;
            float s1 = odd ? uA1 : uB1;
            float r0 = __shfl_xor_sync(0xFFFFFFFFu, s0, 1);
            float r1 = __shfl_xor_sync(0xFFFFFFFFu, s1, 1);
            float w0 = odd ? r0 : uA0;
            float w1 = odd ? r1 : uA1;
            float w2 = odd ? uB0 : r0;
            float w3 = odd ? uB1 : r1;
            float* base = myAgg + nt * 8 + col4;
            if (seg == 0) {
                red4(base, w0, w1, w2, w3);
            } else {
#pragma unroll
                for (int p = 0; p < 5; p++) {
                    if (p < NP) {
                        float yp = Yv[p];
                        red4(base + OFF + p * 64, w0 * yp, w1 * yp, w2 * yp, w3 * yp);
                    }
                }
            }
        }
    }
}

// ---------------- kernel 4: down-projection, pipelined planes -------------------
__global__ void __launch_bounds__(256) k_down(const float* __restrict__ w0,
                                              const float* __restrict__ w1,
                                              const float* __restrict__ w2,
                                              float* __restrict__ out) {
    extern __shared__ float dsm[];
    float* sW    = dsm;            // 4096
    float* sAbuf = dsm + 4096;     // 2 x 2176
    float* sO    = dsm + 8448;     // up to 32 x 324 = 10368

    const int t   = threadIdx.x;
    const int nb  = blockIdx.x * 32;
    const int seg = blockIdx.y;
    const int nplanes = (seg == 0) ? 1 : (seg == 1 ? 3 : 5);
    const int stride  = nplanes;
    const int roff    = (seg == 0) ? 0 : (seg == 1 ? 64 : 256);
    const int ooff4   = (seg == 0) ? 0 : (seg == 1 ? 16 : 64);
    const int ow      = 64 * stride;
    const int rowp    = ow + 4;
    const float* W    = (seg == 0) ? w0 : (seg == 1 ? w1 : w2);

    for (int i = t; i < 4096; i += 256) sW[i] = W[i];

    const int ty = t >> 4, tx = t & 15;
    const int r0 = ty * 2, d0 = tx * 4;

    float rg[8];
#pragma unroll
    for (int j = 0; j < 8; j++) {
        int i = t + j * 256;
        rg[j] = g_agg[(size_t)(nb + (i >> 6)) * 576 + roff + (i & 63)];
    }

    for (int p = 0; p < nplanes; p++) {
        float* sA = sAbuf + (p & 1) * 2176;
#pragma unroll
        for (int j = 0; j < 8; j++) {
            int i = t + j * 256;
            sA[(i >> 6) * 68 + (i & 63)] = rg[j];
        }
        __syncthreads();
        if (p + 1 < nplanes) {
#pragma unroll
            for (int j = 0; j < 8; j++) {
                int i = t + j * 256;
                rg[j] = g_agg[(size_t)(nb + (i >> 6)) * 576 + roff + (p + 1) * 64 + (i & 63)];
            }
        }

        float acc[2][4] = {};
#pragma unroll 8
        for (int k = 0; k < 64; k++) {
            float a0 = sA[r0 * 68 + k];
            float a1 = sA[(r0 + 1) * 68 + k];
            float4 b = *reinterpret_cast<const float4*>(&sW[k * 64 + d0]);
            acc[0][0] += a0 * b.x; acc[0][1] += a0 * b.y; acc[0][2] += a0 * b.z; acc[0][3] += a0 * b.w;
            acc[1][0] += a1 * b.x; acc[1][1] += a1 * b.y; acc[1][2] += a1 * b.z; acc[1][3] += a1 * b.w;
        }
#pragma unroll
        for (int i = 0; i < 2; i++)
#pragma unroll
            for (int j = 0; j < 4; j++)
                sO[(r0 + i) * rowp + (d0 + j) * stride + p] = acc[i][j] * 0.125f;
    }
    __syncthreads();

    const int ow4 = ow >> 2, rowp4 = rowp >> 2;
    const float4* s4 = reinterpret_cast<const float4*>(sO);
    float4*       o4 = reinterpret_cast<float4*>(out);
    for (int i = t; i < 32 * ow4; i += 256) {
        int n = i / ow4, c = i - n * ow4;
        o4[(size_t)(nb + n) * 144 + ooff4 + c] = s4[n * rowp4 + c];
    }
}

// ---------------- launcher ------------------------------------------------------
extern "C" void kernel_launch(void* const* d_in, const int* in_sizes, int n_in,
                              void* d_out, int out_size) {
    const float* vectors    = (const float*)d_in[0];
    const float* node_feats = (const float*)d_in[1];
    const float* radial     = (const float*)d_in[2];
    const int*   senders    = (const int*)  d_in[3];
    const int*   receivers  = (const int*)  d_in[4];
    const float* w_up       = (const float*)d_in[5];
    const float* mlp_w1     = (const float*)d_in[6];
    const float* mlp_w2     = (const float*)d_in[7];
    const float* mlp_w3     = (const float*)d_in[8];
    const float* mlp_w4     = (const float*)d_in[9];
    const float* w_down0    = (const float*)d_in[10];
    const float* w_down1    = (const float*)d_in[11];
    const float* w_down2    = (const float*)d_in[12];
    float* out = (float*)d_out;

    const int FUSED_SMEM = 22592 * 4;    // 90,368 B  -> 2 CTAs/SM
    const int DOWN_SMEM  = 18816 * 4;    // 75,264 B
    cudaFuncSetAttribute(k_fused, cudaFuncAttributeMaxDynamicSharedMemorySize, FUSED_SMEM);
    cudaFuncSetAttribute(k_down,  cudaFuncAttributeMaxDynamicSharedMemorySize, DOWN_SMEM);

    k_init<<<11879, 256>>>(node_feats, w_up, mlp_w1, mlp_w2, mlp_w3, mlp_w4);
    k_fused<<<2500, 256, FUSED_SMEM>>>(radial, vectors, senders, receivers);
    k_down<<<dim3(625, 3), 256, DOWN_SMEM>>>(w_down0, w_down1, w_down2, out);
}